// round 15
// baseline (speedup 1.0000x reference)
#include <cuda_runtime.h>
#include <cuda_bf16.h>
#include <math.h>

#define V_   50000
#define E_   256
#define H_   256
#define G4_  1024
#define HD_  512
#define T_   50
#define B_   128
#define S_   512

typedef unsigned long long u64;
typedef unsigned int u32;

// ---------------------------------------------------------------------------
// Device scratch
// ---------------------------------------------------------------------------
__device__ __nv_bfloat16 g_embb[(size_t)V_ * E_];
__device__ __nv_bfloat16 g_wihb[(size_t)2 * G4_ * E_];
__device__ __nv_bfloat16 g_woutb[(size_t)64 * HD_];        // padded [64][512]
__device__ __nv_bfloat16 g_Gb[(size_t)2 * S_ * B_ * G4_];  // [d][s][b][j]
__device__ __nv_bfloat16 g_hb[(size_t)2 * S_ * B_ * H_];   // [d][s][b][k]
__device__ __align__(16) float g_emis[(size_t)S_ * B_ * T_];
__device__ float g_res[B_];
__device__ u32 g_barcnt[16];    // monotonic arrival counters (16 groups of 4)

// ---------------------------------------------------------------------------
// Helpers
// ---------------------------------------------------------------------------
__device__ __forceinline__ u64 pk2(float lo, float hi) {
    u64 r; asm("mov.b64 %0, {%1, %2};" : "=l"(r) : "f"(lo), "f"(hi)); return r;
}
__device__ __forceinline__ u64 f2ma(u64 a, u64 b, u64 c) {
    u64 d; asm("fma.rn.f32x2 %0, %1, %2, %3;" : "=l"(d) : "l"(a), "l"(b), "l"(c)); return d;
}
__device__ __forceinline__ u64 f2add(u64 a, u64 b) {
    u64 d; asm("add.rn.f32x2 %0, %1, %2;" : "=l"(d) : "l"(a), "l"(b)); return d;
}
__device__ __forceinline__ float2 upk(u64 v) {
    float2 f; asm("mov.b64 {%0, %1}, %2;" : "=f"(f.x), "=f"(f.y) : "l"(v)); return f;
}
__device__ __forceinline__ u32 smem_u32(const void* p) { return (u32)__cvta_generic_to_shared(p); }
__device__ __forceinline__ void cp16(void* smem, const void* g) {
    asm volatile("cp.async.cg.shared.global [%0], [%1], 16;" :: "r"(smem_u32(smem)), "l"(g));
}
#define CP_COMMIT() asm volatile("cp.async.commit_group;")
#define CP_WAITN(n) asm volatile("cp.async.wait_group %0;" :: "n"(n))

__device__ __forceinline__ u32 bfpack(float lo, float hi) {
    u32 r; asm("cvt.rn.bf16x2.f32 %0, %1, %2;" : "=r"(r) : "f"(hi), "f"(lo)); return r;
}
__device__ __forceinline__ float tanhx(float x) {
    float r; asm("tanh.approx.f32 %0, %1;" : "=f"(r) : "f"(x)); return r;
}
__device__ __forceinline__ float sigx(float x) { return 0.5f * tanhx(0.5f * x) + 0.5f; }

__device__ __forceinline__ void ldsm4(u32& r0, u32& r1, u32& r2, u32& r3, u32 addr) {
    asm volatile("ldmatrix.sync.aligned.m8n8.x4.shared.b16 {%0,%1,%2,%3}, [%4];"
                 : "=r"(r0), "=r"(r1), "=r"(r2), "=r"(r3) : "r"(addr));
}
__device__ __forceinline__ void ldsm2(u32& r0, u32& r1, u32 addr) {
    asm volatile("ldmatrix.sync.aligned.m8n8.x2.shared.b16 {%0,%1}, [%2];"
                 : "=r"(r0), "=r"(r1) : "r"(addr));
}
__device__ __forceinline__ void hmma(float* d, u32 a0, u32 a1, u32 a2, u32 a3, u32 b0, u32 b1) {
    asm volatile(
        "mma.sync.aligned.m16n8k16.row.col.f32.bf16.bf16.f32 "
        "{%0,%1,%2,%3}, {%4,%5,%6,%7}, {%8,%9}, {%0,%1,%2,%3};"
        : "+f"(d[0]), "+f"(d[1]), "+f"(d[2]), "+f"(d[3])
        : "r"(a0), "r"(a1), "r"(a2), "r"(a3), "r"(b0), "r"(b1));
}

__device__ __forceinline__ u32 ld_acq(const u32* p) {
    u32 v; asm volatile("ld.acquire.gpu.u32 %0, [%1];" : "=r"(v) : "l"(p) : "memory"); return v;
}
__device__ __forceinline__ u32 atom_add_rel(u32* p, u32 v) {
    u32 o; asm volatile("atom.release.gpu.add.u32 %0, [%1], %2;" : "=r"(o) : "l"(p), "r"(v) : "memory"); return o;
}

// ---------------------------------------------------------------------------
// K0: convert emb + W_ih + W_out(padded to 64 rows) to bf16; reset barriers
// ---------------------------------------------------------------------------
#define EMB2  ((V_ * E_) / 2)
#define WIH2  ((G4_ * E_) / 2)
#define WOUT2 ((64 * HD_) / 2)
__global__ void __launch_bounds__(256) k_convert(
    const float* __restrict__ emb, const float* __restrict__ wf,
    const float* __restrict__ wb,  const float* __restrict__ wo)
{
    if (blockIdx.x == 0 && threadIdx.x < 16) g_barcnt[threadIdx.x] = 0;  // ordered before k_lstm
    int i = blockIdx.x * 256 + threadIdx.x;
    if (i >= EMB2 + 2 * WIH2 + WOUT2) return;
    float2 v; __nv_bfloat162* dst;
    if (i < EMB2)                 { v = ((const float2*)emb)[i];              dst = (__nv_bfloat162*)g_embb + i; }
    else if (i < EMB2 + WIH2)     { v = ((const float2*)wf)[i - EMB2];        dst = (__nv_bfloat162*)g_wihb + (i - EMB2); }
    else if (i < EMB2 + 2 * WIH2) { v = ((const float2*)wb)[i - EMB2 - WIH2]; dst = (__nv_bfloat162*)g_wihb + (i - EMB2); }
    else {
        int j = i - EMB2 - 2 * WIH2;
        int tag = (j * 2) >> 9, k = (j * 2) & 511;
        v.x = (tag < T_) ? wo[(size_t)tag * HD_ + k] : 0.f;
        v.y = (tag < T_) ? wo[(size_t)tag * HD_ + k + 1] : 0.f;
        dst = (__nv_bfloat162*)g_woutb + j;
    }
    *dst = __floats2bfloat162_rn(v.x, v.y);
}

// ---------------------------------------------------------------------------
// K1: input projection via mma.sync bf16 (R14). grid (8 jt, 2 d, 1024), blk 256.
// ---------------------------------------------------------------------------
__global__ void __launch_bounds__(256) k_input(
    const int* __restrict__ sent,
    const float* __restrict__ bih_f, const float* __restrict__ bhh_f,
    const float* __restrict__ bih_b, const float* __restrict__ bhh_b)
{
    extern __shared__ __align__(16) char smraw[];
    char* sm = smraw + ((1024 - (smem_u32(smraw) & 1023)) & 1023);
    char* smB  = sm;                     // 64KB W tile
    char* smA  = sm + 65536;             // 32KB emb tile
    int*  toks = (int*)(sm + 98304);
    float* bsm = (float*)(sm + 98560);

    const int jt = blockIdx.x, d = blockIdx.y;
    const int s  = blockIdx.z >> 1;
    const int bh = blockIdx.z & 1;
    const int j0 = jt * 128;
    const int t = threadIdx.x;
    const int l = t & 31, w = t >> 5;
    const int wm = w & 1, wn = w >> 1;

    if (t < 64) toks[t] = sent[(bh * 64 + t) * S_ + s];
    if (t < 128) {
        const float* bi = d ? bih_b : bih_f;
        const float* bh_ = d ? bhh_b : bhh_f;
        bsm[t] = bi[j0 + t] + bh_[j0 + t];
    }
    __syncthreads();

    for (int i = t; i < 4096; i += 256) {
        int row = i >> 5, c = i & 31;
        cp16(smB + row * 512 + ((c ^ (row & 7)) * 16),
             (const char*)(g_wihb + ((size_t)d * G4_ + j0 + row) * E_) + c * 16);
    }
    for (int i = t; i < 2048; i += 256) {
        int row = i >> 5, c = i & 31;
        cp16(smA + row * 512 + ((c ^ (row & 7)) * 16),
             (const char*)(g_embb + (size_t)toks[row] * E_) + c * 16);
    }
    CP_COMMIT();
    CP_WAITN(0);
    __syncthreads();

    const u32 smB_b = smem_u32(smB), smA_b = smem_u32(smA);

    float acc[2][4][4];
#pragma unroll
    for (int m = 0; m < 2; m++)
#pragma unroll
        for (int n = 0; n < 4; n++)
#pragma unroll
            for (int q = 0; q < 4; q++) acc[m][n][q] = 0.f;

#pragma unroll 4
    for (int kk = 0; kk < 16; kk++) {
        u32 a[2][4];
#pragma unroll
        for (int m = 0; m < 2; m++) {
            int row = wm * 32 + m * 16 + (l & 15);
            int c = kk * 2 + (l >> 4);
            ldsm4(a[m][0], a[m][1], a[m][2], a[m][3],
                  smA_b + row * 512 + ((c ^ (row & 7)) * 16));
        }
#pragma unroll
        for (int nt = 0; nt < 4; nt++) {
            int row = wn * 32 + nt * 8 + (l & 7);
            int c = kk * 2 + ((l >> 3) & 1);
            u32 b0, b1;
            ldsm2(b0, b1, smB_b + row * 512 + ((c ^ (row & 7)) * 16));
#pragma unroll
            for (int m = 0; m < 2; m++)
                hmma(acc[m][nt], a[m][0], a[m][1], a[m][2], a[m][3], b0, b1);
        }
    }

    __nv_bfloat16* Gbase = g_Gb + ((size_t)(d * S_ + s) * B_) * G4_;
#pragma unroll
    for (int m = 0; m < 2; m++)
#pragma unroll
    for (int nt = 0; nt < 4; nt++) {
        int r  = wm * 32 + m * 16 + (l >> 2);
        int jl = wn * 32 + nt * 8 + 2 * (l & 3);
        float b0 = bsm[jl], b1 = bsm[jl + 1];
        size_t bg = (size_t)(bh * 64 + r);
        *(u32*)(Gbase + bg * G4_ + j0 + jl)       = bfpack(acc[m][nt][0] + b0, acc[m][nt][1] + b1);
        *(u32*)(Gbase + (bg + 8) * G4_ + j0 + jl) = bfpack(acc[m][nt][2] + b0, acc[m][nt][3] + b1);
    }
}

// ---------------------------------------------------------------------------
// K2: persistent bidirectional LSTM, batch-group partition. grid 64, blk 128.
// CTA = (d = cta>>5, bg = (cta>>2)&7, us = cta&3): 16 batch rows x 64 units,
// ALL 4 gates local (M=16, N=256, K=256; W slice 128KB smem). Sync domain =
// 4 CTAs sharing (d,bg): groups grp = cta>>2, monotonic counter, 4 arrivals.
// Per step: 8KB h reload + 2KB h store instead of 32KB/32-CTA global round.
// ---------------------------------------------------------------------------
__global__ void __launch_bounds__(128, 1) k_lstm(
    const float* __restrict__ whh_f, const float* __restrict__ whh_b)
{
    extern __shared__ __align__(16) char smraw[];
    char* sm  = smraw + ((1024 - (smem_u32(smraw) & 1023)) & 1023);
    char* smA = sm;                  // 8KB h tile [16 b][512B]
    char* smW = sm + 8192;           // 128KB W slice [256 j][512B]

    const int cta = blockIdx.x;
    const int d   = cta >> 5;
    const int bg  = (cta >> 2) & 7;
    const int us  = cta & 3;
    const int grp = cta >> 2;        // 0..15
    const int b0  = bg * 16;
    const int U0  = us * 64;
    const int t   = threadIdx.x;
    const int l = t & 31, w = t >> 5;
    const float* __restrict__ Wh = d ? whh_b : whh_f;

    // Load W slice: smem row j = g*64 + ul  <-  Wh[g*256 + U0 + ul][k]
    for (int i = t; i < 256 * 64; i += 128) {
        int row = i >> 6, k4 = (i & 63) * 4;
        int g = row >> 6, ul = row & 63;
        float4 v = *(const float4*)&Wh[(size_t)(g * 256 + U0 + ul) * H_ + k4];
        int c = k4 >> 3, off = (k4 * 2) & 15;
        char* p = smW + row * 512 + ((c ^ (row & 7)) * 16) + off;
        *(u32*)p       = bfpack(v.x, v.y);
        *(u32*)(p + 4) = bfpack(v.z, v.w);
    }
    __syncthreads();

    const u32 smA_b = smem_u32(smA), smW_b = smem_u32(smW);
    const int u2 = 2 * (l & 3);      // unit pair base within n-tile of 8

    float cst[8];                    // [un][hi][2]
#pragma unroll
    for (int u = 0; u < 8; u++) cst[u] = 0.f;

    const __nv_bfloat16* Gd = g_Gb + (size_t)d * S_ * B_ * G4_;
    __nv_bfloat16*       Hd = g_hb + (size_t)d * S_ * B_ * H_;

    // gq layout: [hi*8 + g*2 + un]
    u32 gq[16], gqn[16];
    auto gload = [&](u32* dst, int ss) {
        const __nv_bfloat16* Gp = Gd + (size_t)ss * B_ * G4_;
#pragma unroll
        for (int hi = 0; hi < 2; hi++) {
            int b = b0 + (l >> 2) + hi * 8;
#pragma unroll
            for (int g = 0; g < 4; g++)
#pragma unroll
                for (int un = 0; un < 2; un++)
                    dst[hi * 8 + g * 2 + un] =
                        *(const u32*)(Gp + (size_t)b * G4_ + g * 256 + U0 + w * 16 + un * 8 + u2);
        }
    };
    gload(gqn, d ? S_ - 1 : 0);

    for (int step = 0; step < S_; step++) {
        const int s = d ? (S_ - 1 - step) : step;

#pragma unroll
        for (int j = 0; j < 16; j++) gq[j] = gqn[j];

        if (step > 0) {
            const int sp = d ? (s + 1) : (s - 1);
            const char* hsrc = (const char*)(Hd + ((size_t)sp * B_ + b0) * H_);
#pragma unroll
            for (int ch = 0; ch < 2; ch++) {
                for (int i = t; i < 256; i += 128) {
                    int row = i >> 4, c = (i & 15) + ch * 16;
                    cp16(smA + row * 512 + ((c ^ (row & 7)) * 16), hsrc + row * 512 + c * 16);
                }
                CP_COMMIT();
            }
        }

        float acc[8][4];             // n-tile = g*2 + un
#pragma unroll
        for (int n = 0; n < 8; n++)
#pragma unroll
            for (int q = 0; q < 4; q++) acc[n][q] = 0.f;

        if (step > 0) {
            CP_WAITN(1);
            __syncthreads();
#pragma unroll
            for (int kk = 0; kk < 8; kk++) {
                u32 a0r, a1r, a2r, a3r;
                {
                    int row = l & 15;
                    int c = kk * 2 + (l >> 4);
                    ldsm4(a0r, a1r, a2r, a3r, smA_b + row * 512 + ((c ^ (row & 7)) * 16));
                }
#pragma unroll
                for (int nt = 0; nt < 8; nt++) {
                    int row = (nt >> 1) * 64 + w * 16 + (nt & 1) * 8 + (l & 7);
                    int c = kk * 2 + ((l >> 3) & 1);
                    u32 b0r, b1r;
                    ldsm2(b0r, b1r, smW_b + row * 512 + ((c ^ (row & 7)) * 16));
                    hmma(acc[nt], a0r, a1r, a2r, a3r, b0r, b1r);
                }
            }
            CP_WAITN(0);
            __syncthreads();
#pragma unroll
            for (int kk = 8; kk < 16; kk++) {
                u32 a0r, a1r, a2r, a3r;
                {
                    int row = l & 15;
                    int c = kk * 2 + (l >> 4);
                    ldsm4(a0r, a1r, a2r, a3r, smA_b + row * 512 + ((c ^ (row & 7)) * 16));
                }
#pragma unroll
                for (int nt = 0; nt < 8; nt++) {
                    int row = (nt >> 1) * 64 + w * 16 + (nt & 1) * 8 + (l & 7);
                    int c = kk * 2 + ((l >> 3) & 1);
                    u32 b0r, b1r;
                    ldsm2(b0r, b1r, smW_b + row * 512 + ((c ^ (row & 7)) * 16));
                    hmma(acc[nt], a0r, a1r, a2r, a3r, b0r, b1r);
                }
            }
        }

        // combine + store h: thread owns batch rows (l>>2, +8) x units
        // (w*16 + un*8 + u2 + {0,1}) for un in {0,1}; all 4 gates local.
#pragma unroll
        for (int un = 0; un < 2; un++)
#pragma unroll
        for (int hi = 0; hi < 2; hi++) {
            const int br = (l >> 2) + hi * 8;
            const int e = hi * 2;
            float2 gi = __bfloat1622float2(*(const __nv_bfloat162*)&gq[hi * 8 + 0 + un]);
            float2 gf = __bfloat1622float2(*(const __nv_bfloat162*)&gq[hi * 8 + 2 + un]);
            float2 gg = __bfloat1622float2(*(const __nv_bfloat162*)&gq[hi * 8 + 4 + un]);
            float2 go = __bfloat1622float2(*(const __nv_bfloat162*)&gq[hi * 8 + 6 + un]);
            const int ci = un * 4 + hi * 2;
            float c0 = sigx(acc[2 + un][e] + gf.x) * cst[ci]
                     + sigx(acc[0 + un][e] + gi.x) * tanhx(acc[4 + un][e] + gg.x);
            cst[ci] = c0;
            float h0 = sigx(acc[6 + un][e] + go.x) * tanhx(c0);
            float c1 = sigx(acc[2 + un][e + 1] + gf.y) * cst[ci + 1]
                     + sigx(acc[0 + un][e + 1] + gi.y) * tanhx(acc[4 + un][e + 1] + gg.y);
            cst[ci + 1] = c1;
            float h1 = sigx(acc[6 + un][e + 1] + go.y) * tanhx(c1);
            *(u32*)(Hd + ((size_t)s * B_ + b0 + br) * H_ + U0 + w * 16 + un * 8 + u2)
                = bfpack(h0, h1);
        }

        // next-step G prefetch BEFORE the barrier (rides under the wait)
        if (step + 1 < S_) gload(gqn, d ? (S_ - 2 - step) : (step + 1));

        // 4-CTA monotonic-counter barrier
        if (step != S_ - 1) {
            __syncthreads();
            if (t == 0) {
                atom_add_rel(&g_barcnt[grp], 1);
                const u32 tgt = (u32)(4 * (step + 1));
                while ((int)(ld_acq(&g_barcnt[grp]) - tgt) < 0) { }
            }
            __syncthreads();
        }
    }
}

// ---------------------------------------------------------------------------
// K3: emissions via mma.sync (R14). grid 512 (s), block 128.
// ---------------------------------------------------------------------------
__global__ void __launch_bounds__(128) k_emis(const float* __restrict__ bo)
{
    extern __shared__ __align__(16) char smraw[];
    char* sm = smraw + ((1024 - (smem_u32(smraw) & 1023)) & 1023);
    char* smW  = sm;
    char* smA0 = sm + 65536;
    char* smA1 = sm + 131072;
    float* bsm = (float*)(sm + 196608);

    const int s = blockIdx.x;
    const int t = threadIdx.x;
    const int l = t & 31, w = t >> 5;

    if (t < 64) bsm[t] = (t < T_) ? bo[t] : 0.f;

    for (int i = t; i < 4096; i += 128) {
        int row = i >> 6, c = i & 63;
        cp16(smW + row * 1024 + ((c ^ (row & 7)) * 16),
             (const char*)g_woutb + row * 1024 + c * 16);
    }
    CP_COMMIT();
    for (int i = t; i < 4096; i += 128) {
        int row = i >> 5, c = i & 31;
        cp16(smA0 + row * 512 + ((c ^ (row & 7)) * 16),
             (const char*)(g_hb + ((size_t)s * B_ + row) * H_) + c * 16);
    }
    CP_COMMIT();
    for (int i = t; i < 4096; i += 128) {
        int row = i >> 5, c = i & 31;
        cp16(smA1 + row * 512 + ((c ^ (row & 7)) * 16),
             (const char*)(g_hb + (size_t)S_ * B_ * H_ + ((size_t)s * B_ + row) * H_) + c * 16);
    }
    CP_COMMIT();

    const u32 smW_b = smem_u32(smW);

    float acc[2][8][4];
#pragma unroll
    for (int m = 0; m < 2; m++)
#pragma unroll
        for (int n = 0; n < 8; n++)
#pragma unroll
            for (int q = 0; q < 4; q++) acc[m][n][q] = 0.f;

    auto stage = [&](u32 smA_b, int wc0) {
#pragma unroll 4
        for (int kk = 0; kk < 16; kk++) {
            u32 a[2][4];
#pragma unroll
            for (int m = 0; m < 2; m++) {
                int row = w * 32 + m * 16 + (l & 15);
                int c = kk * 2 + (l >> 4);
                ldsm4(a[m][0], a[m][1], a[m][2], a[m][3],
                      smA_b + row * 512 + ((c ^ (row & 7)) * 16));
            }
#pragma unroll
            for (int nt = 0; nt < 8; nt++) {
                int row = nt * 8 + (l & 7);
                int c = wc0 + kk * 2 + ((l >> 3) & 1);
                u32 b0, b1;
                ldsm2(b0, b1, smW_b + row * 1024 + ((c ^ (row & 7)) * 16));
#pragma unroll
                for (int m = 0; m < 2; m++)
                    hmma(acc[m][nt], a[m][0], a[m][1], a[m][2], a[m][3], b0, b1);
            }
        }
    };

    CP_WAITN(1);
    __syncthreads();
    stage(smem_u32(smA0), 0);
    CP_WAITN(0);
    __syncthreads();
    stage(smem_u32(smA1), 32);

#pragma unroll
    for (int m = 0; m < 2; m++)
#pragma unroll
    for (int nt = 0; nt < 8; nt++) {
        int r  = w * 32 + m * 16 + (l >> 2);
        int jl = nt * 8 + 2 * (l & 3);
        if (jl < T_) {
            float b0 = bsm[jl], b1 = bsm[jl + 1];
            *(float2*)(g_emis + ((size_t)s * B_ + r) * T_ + jl)     = make_float2(acc[m][nt][0] + b0, acc[m][nt][1] + b1);
            *(float2*)(g_emis + ((size_t)s * B_ + r + 8) * T_ + jl) = make_float2(acc[m][nt][2] + b0, acc[m][nt][3] + b1);
        }
    }
}

// ---------------------------------------------------------------------------
// K4: CRF — one warp per batch element, 128 CTAs; exp(trans) in registers.
// ---------------------------------------------------------------------------
__global__ void __launch_bounds__(32) k_crf(
    const float* __restrict__ trans, const float* __restrict__ start_t,
    const float* __restrict__ end_t, const int* __restrict__ tags)
{
    __shared__ float pw[64];

    const int b = blockIdx.x;
    const int l = threadIdx.x;
    const bool v1 = (l + 32 < T_);

    u64 eT[T_];
#pragma unroll
    for (int tt = 0; tt < T_; tt++) {
        float e0 = expf(trans[tt * T_ + l]);
        float e1 = v1 ? expf(trans[tt * T_ + l + 32]) : 0.f;
        eT[tt] = pk2(e0, e1);
    }

    float a0 = start_t[l] + g_emis[(size_t)b * T_ + l];
    float a1 = v1 ? (start_t[l + 32] + g_emis[(size_t)b * T_ + l + 32]) : -1e30f;

    float e0n = g_emis[((size_t)B_ + b) * T_ + l];
    float e1n = v1 ? g_emis[((size_t)B_ + b) * T_ + l + 32] : 0.f;

    for (int s = 1; s < S_; s++) {
        float e0 = e0n, e1 = e1n;
        if (s + 1 < S_) {
            const float* es = g_emis + ((size_t)(s + 1) * B_ + b) * T_;
            e0n = es[l];
            e1n = v1 ? es[l + 32] : 0.f;
        }

        float m = __shfl_sync(0xffffffffu, a0, 0);
        pw[l]      = __expf(a0 - m);
        pw[l + 32] = v1 ? __expf(a1 - m) : 0.f;
        __syncwarp();

        u64 q0 = 0ull, q1 = 0ull, q2 = 0ull, q3 = 0ull;
#pragma unroll
        for (int tt = 0; tt < 48; tt += 4) {
            q0 = f2ma(pk2(pw[tt],     pw[tt]),     eT[tt],     q0);
            q1 = f2ma(pk2(pw[tt + 1], pw[tt + 1]), eT[tt + 1], q1);
            q2 = f2ma(pk2(pw[tt + 2], pw[tt + 2]), eT[tt + 2], q2);
            q3 = f2ma(pk2(pw[tt + 3], pw[tt + 3]), eT[tt + 3], q3);
        }
        q0 = f2ma(pk2(pw[48], pw[48]), eT[48], q0);
        q1 = f2ma(pk2(pw[49], pw[49]), eT[49], q1);
        float2 qf = upk(f2add(f2add(q0, q1), f2add(q2, q3)));
        a0 = m + __logf(qf.x) + e0;
        a1 = v1 ? (m + __logf(qf.y) + e1) : -1e30f;
        __syncwarp();
    }

    float vv0 = a0 + end_t[l];
    float vv1 = v1 ? (a1 + end_t[l + 32]) : -1e30f;
    float m = fmaxf(vv0, vv1);
#pragma unroll
    for (int o = 16; o; o >>= 1) m = fmaxf(m, __shfl_xor_sync(0xffffffffu, m, o));
    float e = __expf(vv0 - m) + (v1 ? __expf(vv1 - m) : 0.f);
#pragma unroll
    for (int o = 16; o; o >>= 1) e += __shfl_xor_sync(0xffffffffu, e, o);
    float logZ = m + __logf(e);

    float acc = 0.f;
    for (int s = 1 + l; s < S_; s += 32) {
        int tp = tags[b * S_ + s - 1];
        int tc = tags[b * S_ + s];
        acc += trans[tp * T_ + tc] + g_emis[((size_t)s * B_ + b) * T_ + tc];
    }
#pragma unroll
    for (int o = 16; o; o >>= 1) acc += __shfl_xor_sync(0xffffffffu, acc, o);

    if (l == 0) {
        int t0 = tags[b * S_];
        int tl = tags[b * S_ + S_ - 1];
        g_res[b] = logZ - (start_t[t0] + g_emis[(size_t)b * T_ + t0] + acc + end_t[tl]);
    }
}

// ---------------------------------------------------------------------------
// K5: final mean
// ---------------------------------------------------------------------------
__global__ void k_final(float* __restrict__ out)
{
    __shared__ float red[4];
    int t = threadIdx.x;
    float v = g_res[t];
#pragma unroll
    for (int o = 16; o; o >>= 1) v += __shfl_xor_sync(0xffffffffu, v, o);
    if ((t & 31) == 0) red[t >> 5] = v;
    __syncthreads();
    if (t == 0) out[0] = (red[0] + red[1] + red[2] + red[3]) * (1.f / (float)B_);
}

// ---------------------------------------------------------------------------
// Launch
// ---------------------------------------------------------------------------
extern "C" void kernel_launch(void* const* d_in, const int* in_sizes, int n_in,
                              void* d_out, int out_size)
{
    const int*   sent  = (const int*)  d_in[0];
    const int*   tags  = (const int*)  d_in[1];
    const float* emb   = (const float*)d_in[3];
    const float* wih_f = (const float*)d_in[4];
    const float* whh_f = (const float*)d_in[5];
    const float* bih_f = (const float*)d_in[6];
    const float* bhh_f = (const float*)d_in[7];
    const float* wih_b = (const float*)d_in[8];
    const float* whh_b = (const float*)d_in[9];
    const float* bih_b = (const float*)d_in[10];
    const float* bhh_b = (const float*)d_in[11];
    const float* Wout  = (const float*)d_in[12];
    const float* bout  = (const float*)d_in[13];
    const float* strt  = (const float*)d_in[14];
    const float* endt  = (const float*)d_in[15];
    const float* trans = (const float*)d_in[16];
    float* out = (float*)d_out;

    const int input_smem = 100352;
    const int lstm_smem  = 8192 + 131072 + 1024;   // h tile + W slice + align
    const int emis_smem  = 197888;
    cudaFuncSetAttribute(k_input, cudaFuncAttributeMaxDynamicSharedMemorySize, input_smem);
    cudaFuncSetAttribute(k_lstm,  cudaFuncAttributeMaxDynamicSharedMemorySize, lstm_smem);
    cudaFuncSetAttribute(k_emis,  cudaFuncAttributeMaxDynamicSharedMemorySize, emis_smem);

    int nconv = (EMB2 + 2 * WIH2 + WOUT2 + 255) / 256;
    k_convert<<<nconv, 256>>>(emb, wih_f, wih_b, Wout);
    k_input<<<dim3(8, 2, 1024), 256, input_smem>>>(sent, bih_f, bhh_f, bih_b, bhh_b);
    k_lstm<<<64, 128, lstm_smem>>>(whh_f, whh_b);
    k_emis<<<512, 128, emis_smem>>>(bout);
    k_crf<<<128, 32>>>(trans, strt, endt, tags);
    k_final<<<1, 128>>>(out);
}

// round 16
// speedup vs baseline: 1.2022x; 1.2022x over previous
#include <cuda_runtime.h>
#include <cuda_bf16.h>
#include <math.h>

#define V_   50000
#define E_   256
#define H_   256
#define G4_  1024
#define HD_  512
#define T_   50
#define B_   128
#define S_   512

typedef unsigned long long u64;
typedef unsigned int u32;

// ---------------------------------------------------------------------------
// Device scratch
// ---------------------------------------------------------------------------
__device__ __nv_bfloat16 g_embb[(size_t)V_ * E_];
__device__ __nv_bfloat16 g_wihb[(size_t)2 * G4_ * E_];
__device__ __nv_bfloat16 g_woutb[(size_t)64 * HD_];        // padded [64][512]
__device__ __nv_bfloat16 g_Gb[(size_t)2 * S_ * B_ * G4_];  // [d][s][b][j]
__device__ __nv_bfloat16 g_hb[(size_t)2 * S_ * B_ * H_];   // [d][s][b][k]
__device__ __align__(16) float g_emis[(size_t)S_ * B_ * T_];
__device__ float g_res[B_];

// ---------------------------------------------------------------------------
// Helpers
// ---------------------------------------------------------------------------
__device__ __forceinline__ u64 pk2(float lo, float hi) {
    u64 r; asm("mov.b64 %0, {%1, %2};" : "=l"(r) : "f"(lo), "f"(hi)); return r;
}
__device__ __forceinline__ u64 f2ma(u64 a, u64 b, u64 c) {
    u64 d; asm("fma.rn.f32x2 %0, %1, %2, %3;" : "=l"(d) : "l"(a), "l"(b), "l"(c)); return d;
}
__device__ __forceinline__ u64 f2add(u64 a, u64 b) {
    u64 d; asm("add.rn.f32x2 %0, %1, %2;" : "=l"(d) : "l"(a), "l"(b)); return d;
}
__device__ __forceinline__ float2 upk(u64 v) {
    float2 f; asm("mov.b64 {%0, %1}, %2;" : "=f"(f.x), "=f"(f.y) : "l"(v)); return f;
}
__device__ __forceinline__ u32 smem_u32(const void* p) { return (u32)__cvta_generic_to_shared(p); }
__device__ __forceinline__ void cp16(void* smem, const void* g) {
    asm volatile("cp.async.cg.shared.global [%0], [%1], 16;" :: "r"(smem_u32(smem)), "l"(g));
}
#define CP_COMMIT() asm volatile("cp.async.commit_group;")
#define CP_WAITN(n) asm volatile("cp.async.wait_group %0;" :: "n"(n))

__device__ __forceinline__ u32 bfpack(float lo, float hi) {
    u32 r; asm("cvt.rn.bf16x2.f32 %0, %1, %2;" : "=r"(r) : "f"(hi), "f"(lo)); return r;
}
__device__ __forceinline__ float tanhx(float x) {
    float r; asm("tanh.approx.f32 %0, %1;" : "=f"(r) : "f"(x)); return r;
}
__device__ __forceinline__ float sigx(float x) { return 0.5f * tanhx(0.5f * x) + 0.5f; }

__device__ __forceinline__ void ldsm4(u32& r0, u32& r1, u32& r2, u32& r3, u32 addr) {
    asm volatile("ldmatrix.sync.aligned.m8n8.x4.shared.b16 {%0,%1,%2,%3}, [%4];"
                 : "=r"(r0), "=r"(r1), "=r"(r2), "=r"(r3) : "r"(addr));
}
__device__ __forceinline__ void ldsm2(u32& r0, u32& r1, u32 addr) {
    asm volatile("ldmatrix.sync.aligned.m8n8.x2.shared.b16 {%0,%1}, [%2];"
                 : "=r"(r0), "=r"(r1) : "r"(addr));
}
__device__ __forceinline__ void hmma(float* d, u32 a0, u32 a1, u32 a2, u32 a3, u32 b0, u32 b1) {
    asm volatile(
        "mma.sync.aligned.m16n8k16.row.col.f32.bf16.bf16.f32 "
        "{%0,%1,%2,%3}, {%4,%5,%6,%7}, {%8,%9}, {%0,%1,%2,%3};"
        : "+f"(d[0]), "+f"(d[1]), "+f"(d[2]), "+f"(d[3])
        : "r"(a0), "r"(a1), "r"(a2), "r"(a3), "r"(b0), "r"(b1));
}

// ---------------------------------------------------------------------------
// K0: convert emb + W_ih + W_out(padded to 64 rows) to bf16
// ---------------------------------------------------------------------------
#define EMB2  ((V_ * E_) / 2)
#define WIH2  ((G4_ * E_) / 2)
#define WOUT2 ((64 * HD_) / 2)
__global__ void __launch_bounds__(256) k_convert(
    const float* __restrict__ emb, const float* __restrict__ wf,
    const float* __restrict__ wb,  const float* __restrict__ wo)
{
    int i = blockIdx.x * 256 + threadIdx.x;
    if (i >= EMB2 + 2 * WIH2 + WOUT2) return;
    float2 v; __nv_bfloat162* dst;
    if (i < EMB2)                 { v = ((const float2*)emb)[i];              dst = (__nv_bfloat162*)g_embb + i; }
    else if (i < EMB2 + WIH2)     { v = ((const float2*)wf)[i - EMB2];        dst = (__nv_bfloat162*)g_wihb + (i - EMB2); }
    else if (i < EMB2 + 2 * WIH2) { v = ((const float2*)wb)[i - EMB2 - WIH2]; dst = (__nv_bfloat162*)g_wihb + (i - EMB2); }
    else {
        int j = i - EMB2 - 2 * WIH2;
        int tag = (j * 2) >> 9, k = (j * 2) & 511;
        v.x = (tag < T_) ? wo[(size_t)tag * HD_ + k] : 0.f;
        v.y = (tag < T_) ? wo[(size_t)tag * HD_ + k + 1] : 0.f;
        dst = (__nv_bfloat162*)g_woutb + j;
    }
    *dst = __floats2bfloat162_rn(v.x, v.y);
}

// ---------------------------------------------------------------------------
// K1: input projection via mma.sync bf16. grid (8 jt, 2 d, 1024), blk 256.
// ---------------------------------------------------------------------------
__global__ void __launch_bounds__(256) k_input(
    const int* __restrict__ sent,
    const float* __restrict__ bih_f, const float* __restrict__ bhh_f,
    const float* __restrict__ bih_b, const float* __restrict__ bhh_b)
{
    extern __shared__ __align__(16) char smraw[];
    char* sm = smraw + ((1024 - (smem_u32(smraw) & 1023)) & 1023);
    char* smB  = sm;                     // 64KB W tile
    char* smA  = sm + 65536;             // 32KB emb tile
    int*  toks = (int*)(sm + 98304);
    float* bsm = (float*)(sm + 98560);

    const int jt = blockIdx.x, d = blockIdx.y;
    const int s  = blockIdx.z >> 1;
    const int bh = blockIdx.z & 1;
    const int j0 = jt * 128;
    const int t = threadIdx.x;
    const int l = t & 31, w = t >> 5;
    const int wm = w & 1, wn = w >> 1;

    if (t < 64) toks[t] = sent[(bh * 64 + t) * S_ + s];
    if (t < 128) {
        const float* bi = d ? bih_b : bih_f;
        const float* bh_ = d ? bhh_b : bhh_f;
        bsm[t] = bi[j0 + t] + bh_[j0 + t];
    }
    __syncthreads();

    for (int i = t; i < 4096; i += 256) {
        int row = i >> 5, c = i & 31;
        cp16(smB + row * 512 + ((c ^ (row & 7)) * 16),
             (const char*)(g_wihb + ((size_t)d * G4_ + j0 + row) * E_) + c * 16);
    }
    for (int i = t; i < 2048; i += 256) {
        int row = i >> 5, c = i & 31;
        cp16(smA + row * 512 + ((c ^ (row & 7)) * 16),
             (const char*)(g_embb + (size_t)toks[row] * E_) + c * 16);
    }
    CP_COMMIT();
    CP_WAITN(0);
    __syncthreads();

    const u32 smB_b = smem_u32(smB), smA_b = smem_u32(smA);

    float acc[2][4][4];
#pragma unroll
    for (int m = 0; m < 2; m++)
#pragma unroll
        for (int n = 0; n < 4; n++)
#pragma unroll
            for (int q = 0; q < 4; q++) acc[m][n][q] = 0.f;

#pragma unroll 4
    for (int kk = 0; kk < 16; kk++) {
        u32 a[2][4];
#pragma unroll
        for (int m = 0; m < 2; m++) {
            int row = wm * 32 + m * 16 + (l & 15);
            int c = kk * 2 + (l >> 4);
            ldsm4(a[m][0], a[m][1], a[m][2], a[m][3],
                  smA_b + row * 512 + ((c ^ (row & 7)) * 16));
        }
#pragma unroll
        for (int nt = 0; nt < 4; nt++) {
            int row = wn * 32 + nt * 8 + (l & 7);
            int c = kk * 2 + ((l >> 3) & 1);
            u32 b0, b1;
            ldsm2(b0, b1, smB_b + row * 512 + ((c ^ (row & 7)) * 16));
#pragma unroll
            for (int m = 0; m < 2; m++)
                hmma(acc[m][nt], a[m][0], a[m][1], a[m][2], a[m][3], b0, b1);
        }
    }

    __nv_bfloat16* Gbase = g_Gb + ((size_t)(d * S_ + s) * B_) * G4_;
#pragma unroll
    for (int m = 0; m < 2; m++)
#pragma unroll
    for (int nt = 0; nt < 4; nt++) {
        int r  = wm * 32 + m * 16 + (l >> 2);
        int jl = wn * 32 + nt * 8 + 2 * (l & 3);
        float b0 = bsm[jl], b1 = bsm[jl + 1];
        size_t bg = (size_t)(bh * 64 + r);
        *(u32*)(Gbase + bg * G4_ + j0 + jl)       = bfpack(acc[m][nt][0] + b0, acc[m][nt][1] + b1);
        *(u32*)(Gbase + (bg + 8) * G4_ + j0 + jl) = bfpack(acc[m][nt][2] + b0, acc[m][nt][3] + b1);
    }
}

// ---------------------------------------------------------------------------
// K2: persistent bidirectional LSTM with DSMEM clusters. grid 64 (16 clusters
// of 4), block 128. CTA = (d = cta>>5, bg = (cta>>2)&7, us = cta&3 = cluster
// rank): 16 batch rows x 64 units, all 4 gates local (M=16, N=256, K=256).
// h exchange: each CTA writes its h slice into ALL 4 peers' smem via
// mapa/st.shared::cluster into a DOUBLE-BUFFERED A-tile; one cluster barrier
// per step (G prefetch issued between arrive and wait). No L2 round trip,
// no cp.async in the loop, no atomic barrier.
// ---------------------------------------------------------------------------
__global__ void __launch_bounds__(128, 1) __cluster_dims__(4, 1, 1)
k_lstm(const float* __restrict__ whh_f, const float* __restrict__ whh_b)
{
    extern __shared__ __align__(16) char smraw[];
    char* sm   = smraw + ((1024 - (smem_u32(smraw) & 1023)) & 1023);
    char* smA0 = sm;                 // 8KB h tile buf0 [16 b][512B]
    char* smA1 = sm + 8192;          // 8KB h tile buf1
    char* smW  = sm + 16384;         // 128KB W slice [256 j][512B]

    const int cta = blockIdx.x;
    const int d   = cta >> 5;
    const int bg  = (cta >> 2) & 7;
    const int b0  = bg * 16;
    const int us  = cta & 3;
    const int U0  = us * 64;
    const int t   = threadIdx.x;
    const int l = t & 31, w = t >> 5;
    const float* __restrict__ Wh = d ? whh_b : whh_f;

    // Load W slice: smem row j = g*64 + ul  <-  Wh[g*256 + U0 + ul][k]
    for (int i = t; i < 256 * 64; i += 128) {
        int row = i >> 6, k4 = (i & 63) * 4;
        int g = row >> 6, ul = row & 63;
        float4 v = *(const float4*)&Wh[(size_t)(g * 256 + U0 + ul) * H_ + k4];
        int c = k4 >> 3, off = (k4 * 2) & 15;
        char* p = smW + row * 512 + ((c ^ (row & 7)) * 16) + off;
        *(u32*)p       = bfpack(v.x, v.y);
        *(u32*)(p + 4) = bfpack(v.z, v.w);
    }
    {   // zero buf0 (step-0 h_prev = 0)
        uint4 z = make_uint4(0, 0, 0, 0);
        for (int i = t; i < 512; i += 128) ((uint4*)smA0)[i] = z;
    }
    __syncthreads();

    const u32 smA0_b = smem_u32(smA0), smA1_b = smem_u32(smA1), smW_b = smem_u32(smW);
    const int u2 = 2 * (l & 3);

    float cst[8];
#pragma unroll
    for (int u = 0; u < 8; u++) cst[u] = 0.f;

    const __nv_bfloat16* Gd = g_Gb + (size_t)d * S_ * B_ * G4_;
    __nv_bfloat16*       Hd = g_hb + (size_t)d * S_ * B_ * H_;

    // gq layout: [hi*8 + g*2 + un]
    u32 gq[16], gqn[16];
    auto gload = [&](u32* dst, int ss) {
        const __nv_bfloat16* Gp = Gd + (size_t)ss * B_ * G4_;
#pragma unroll
        for (int hi = 0; hi < 2; hi++) {
            int b = b0 + (l >> 2) + hi * 8;
#pragma unroll
            for (int g = 0; g < 4; g++)
#pragma unroll
                for (int un = 0; un < 2; un++)
                    dst[hi * 8 + g * 2 + un] =
                        *(const u32*)(Gp + (size_t)b * G4_ + g * 256 + U0 + w * 16 + un * 8 + u2);
        }
    };
    gload(gqn, d ? S_ - 1 : 0);

    // write h value into all 4 cluster CTAs' write-buffer
    auto stpeer = [&](u32 laddr, u32 v) {
#pragma unroll
        for (int r = 0; r < 4; r++) {
            u32 ra;
            asm("mapa.shared::cluster.u32 %0, %1, %2;" : "=r"(ra) : "r"(laddr), "r"(r));
            asm volatile("st.shared::cluster.u32 [%0], %1;" :: "r"(ra), "r"(v) : "memory");
        }
    };

    for (int step = 0; step < S_; step++) {
        const int s = d ? (S_ - 1 - step) : step;
        const u32 rdA = (step & 1) ? smA1_b : smA0_b;
        const u32 wrA = (step & 1) ? smA0_b : smA1_b;

#pragma unroll
        for (int j = 0; j < 16; j++) gq[j] = gqn[j];

        float acc[8][4];
#pragma unroll
        for (int n = 0; n < 8; n++)
#pragma unroll
            for (int q = 0; q < 4; q++) acc[n][q] = 0.f;

        if (step > 0) {
#pragma unroll
            for (int kk = 0; kk < 16; kk++) {
                u32 a0r, a1r, a2r, a3r;
                {
                    int row = l & 15;
                    int c = kk * 2 + (l >> 4);
                    ldsm4(a0r, a1r, a2r, a3r, rdA + row * 512 + ((c ^ (row & 7)) * 16));
                }
#pragma unroll
                for (int nt = 0; nt < 8; nt++) {
                    int row = (nt >> 1) * 64 + w * 16 + (nt & 1) * 8 + (l & 7);
                    int c = kk * 2 + ((l >> 3) & 1);
                    u32 b0r, b1r;
                    ldsm2(b0r, b1r, smW_b + row * 512 + ((c ^ (row & 7)) * 16));
                    hmma(acc[nt], a0r, a1r, a2r, a3r, b0r, b1r);
                }
            }
        }

        // combine + store h (global for k_emis, DSMEM peers for next step)
        const bool more = (step + 1 < S_);
#pragma unroll
        for (int un = 0; un < 2; un++)
#pragma unroll
        for (int hi = 0; hi < 2; hi++) {
            const int br = (l >> 2) + hi * 8;
            const int e = hi * 2;
            float2 gi = __bfloat1622float2(*(const __nv_bfloat162*)&gq[hi * 8 + 0 + un]);
            float2 gf = __bfloat1622float2(*(const __nv_bfloat162*)&gq[hi * 8 + 2 + un]);
            float2 gg = __bfloat1622float2(*(const __nv_bfloat162*)&gq[hi * 8 + 4 + un]);
            float2 go = __bfloat1622float2(*(const __nv_bfloat162*)&gq[hi * 8 + 6 + un]);
            const int ci = un * 4 + hi * 2;
            float c0 = sigx(acc[2 + un][e] + gf.x) * cst[ci]
                     + sigx(acc[0 + un][e] + gi.x) * tanhx(acc[4 + un][e] + gg.x);
            cst[ci] = c0;
            float h0 = sigx(acc[6 + un][e] + go.x) * tanhx(c0);
            float c1 = sigx(acc[2 + un][e + 1] + gf.y) * cst[ci + 1]
                     + sigx(acc[0 + un][e + 1] + gi.y) * tanhx(acc[4 + un][e + 1] + gg.y);
            cst[ci + 1] = c1;
            float h1 = sigx(acc[6 + un][e + 1] + go.y) * tanhx(c1);
            u32 hv = bfpack(h0, h1);
            *(u32*)(Hd + ((size_t)s * B_ + b0 + br) * H_ + U0 + w * 16 + un * 8 + u2) = hv;
            if (more) {
                int bo = 2 * (U0 + w * 16 + un * 8 + u2);
                u32 laddr = wrA + br * 512 + ((((bo >> 4) ^ (br & 7)) << 4) | (bo & 15));
                stpeer(laddr, hv);
            }
        }

        // one cluster barrier per step; G prefetch rides between arrive/wait
        if (more) {
            asm volatile("barrier.cluster.arrive.aligned;" ::: "memory");
            gload(gqn, d ? (S_ - 2 - step) : (step + 1));
            asm volatile("barrier.cluster.wait.aligned;" ::: "memory");
        }
    }
}

// ---------------------------------------------------------------------------
// K3: emissions via mma.sync. grid 512 (s), block 128.
// ---------------------------------------------------------------------------
__global__ void __launch_bounds__(128) k_emis(const float* __restrict__ bo)
{
    extern __shared__ __align__(16) char smraw[];
    char* sm = smraw + ((1024 - (smem_u32(smraw) & 1023)) & 1023);
    char* smW  = sm;
    char* smA0 = sm + 65536;
    char* smA1 = sm + 131072;
    float* bsm = (float*)(sm + 196608);

    const int s = blockIdx.x;
    const int t = threadIdx.x;
    const int l = t & 31, w = t >> 5;

    if (t < 64) bsm[t] = (t < T_) ? bo[t] : 0.f;

    for (int i = t; i < 4096; i += 128) {
        int row = i >> 6, c = i & 63;
        cp16(smW + row * 1024 + ((c ^ (row & 7)) * 16),
             (const char*)g_woutb + row * 1024 + c * 16);
    }
    CP_COMMIT();
    for (int i = t; i < 4096; i += 128) {
        int row = i >> 5, c = i & 31;
        cp16(smA0 + row * 512 + ((c ^ (row & 7)) * 16),
             (const char*)(g_hb + ((size_t)s * B_ + row) * H_) + c * 16);
    }
    CP_COMMIT();
    for (int i = t; i < 4096; i += 128) {
        int row = i >> 5, c = i & 31;
        cp16(smA1 + row * 512 + ((c ^ (row & 7)) * 16),
             (const char*)(g_hb + (size_t)S_ * B_ * H_ + ((size_t)s * B_ + row) * H_) + c * 16);
    }
    CP_COMMIT();

    const u32 smW_b = smem_u32(smW);

    float acc[2][8][4];
#pragma unroll
    for (int m = 0; m < 2; m++)
#pragma unroll
        for (int n = 0; n < 8; n++)
#pragma unroll
            for (int q = 0; q < 4; q++) acc[m][n][q] = 0.f;

    auto stage = [&](u32 smA_b, int wc0) {
#pragma unroll 4
        for (int kk = 0; kk < 16; kk++) {
            u32 a[2][4];
#pragma unroll
            for (int m = 0; m < 2; m++) {
                int row = w * 32 + m * 16 + (l & 15);
                int c = kk * 2 + (l >> 4);
                ldsm4(a[m][0], a[m][1], a[m][2], a[m][3],
                      smA_b + row * 512 + ((c ^ (row & 7)) * 16));
            }
#pragma unroll
            for (int nt = 0; nt < 8; nt++) {
                int row = nt * 8 + (l & 7);
                int c = wc0 + kk * 2 + ((l >> 3) & 1);
                u32 b0, b1;
                ldsm2(b0, b1, smW_b + row * 1024 + ((c ^ (row & 7)) * 16));
#pragma unroll
                for (int m = 0; m < 2; m++)
                    hmma(acc[m][nt], a[m][0], a[m][1], a[m][2], a[m][3], b0, b1);
            }
        }
    };

    CP_WAITN(1);
    __syncthreads();
    stage(smem_u32(smA0), 0);
    CP_WAITN(0);
    __syncthreads();
    stage(smem_u32(smA1), 32);

#pragma unroll
    for (int m = 0; m < 2; m++)
#pragma unroll
    for (int nt = 0; nt < 8; nt++) {
        int r  = w * 32 + m * 16 + (l >> 2);
        int jl = nt * 8 + 2 * (l & 3);
        if (jl < T_) {
            float b0 = bsm[jl], b1 = bsm[jl + 1];
            *(float2*)(g_emis + ((size_t)s * B_ + r) * T_ + jl)     = make_float2(acc[m][nt][0] + b0, acc[m][nt][1] + b1);
            *(float2*)(g_emis + ((size_t)s * B_ + r + 8) * T_ + jl) = make_float2(acc[m][nt][2] + b0, acc[m][nt][3] + b1);
        }
    }
}

// ---------------------------------------------------------------------------
// K4: CRF — one warp per batch element, 128 CTAs; exp(trans) in registers.
// ---------------------------------------------------------------------------
__global__ void __launch_bounds__(32) k_crf(
    const float* __restrict__ trans, const float* __restrict__ start_t,
    const float* __restrict__ end_t, const int* __restrict__ tags)
{
    __shared__ float pw[64];

    const int b = blockIdx.x;
    const int l = threadIdx.x;
    const bool v1 = (l + 32 < T_);

    u64 eT[T_];
#pragma unroll
    for (int tt = 0; tt < T_; tt++) {
        float e0 = expf(trans[tt * T_ + l]);
        float e1 = v1 ? expf(trans[tt * T_ + l + 32]) : 0.f;
        eT[tt] = pk2(e0, e1);
    }

    float a0 = start_t[l] + g_emis[(size_t)b * T_ + l];
    float a1 = v1 ? (start_t[l + 32] + g_emis[(size_t)b * T_ + l + 32]) : -1e30f;

    float e0n = g_emis[((size_t)B_ + b) * T_ + l];
    float e1n = v1 ? g_emis[((size_t)B_ + b) * T_ + l + 32] : 0.f;

    for (int s = 1; s < S_; s++) {
        float e0 = e0n, e1 = e1n;
        if (s + 1 < S_) {
            const float* es = g_emis + ((size_t)(s + 1) * B_ + b) * T_;
            e0n = es[l];
            e1n = v1 ? es[l + 32] : 0.f;
        }

        float m = __shfl_sync(0xffffffffu, a0, 0);
        pw[l]      = __expf(a0 - m);
        pw[l + 32] = v1 ? __expf(a1 - m) : 0.f;
        __syncwarp();

        u64 q0 = 0ull, q1 = 0ull, q2 = 0ull, q3 = 0ull;
#pragma unroll
        for (int tt = 0; tt < 48; tt += 4) {
            q0 = f2ma(pk2(pw[tt],     pw[tt]),     eT[tt],     q0);
            q1 = f2ma(pk2(pw[tt + 1], pw[tt + 1]), eT[tt + 1], q1);
            q2 = f2ma(pk2(pw[tt + 2], pw[tt + 2]), eT[tt + 2], q2);
            q3 = f2ma(pk2(pw[tt + 3], pw[tt + 3]), eT[tt + 3], q3);
        }
        q0 = f2ma(pk2(pw[48], pw[48]), eT[48], q0);
        q1 = f2ma(pk2(pw[49], pw[49]), eT[49], q1);
        float2 qf = upk(f2add(f2add(q0, q1), f2add(q2, q3)));
        a0 = m + __logf(qf.x) + e0;
        a1 = v1 ? (m + __logf(qf.y) + e1) : -1e30f;
        __syncwarp();
    }

    float vv0 = a0 + end_t[l];
    float vv1 = v1 ? (a1 + end_t[l + 32]) : -1e30f;
    float m = fmaxf(vv0, vv1);
#pragma unroll
    for (int o = 16; o; o >>= 1) m = fmaxf(m, __shfl_xor_sync(0xffffffffu, m, o));
    float e = __expf(vv0 - m) + (v1 ? __expf(vv1 - m) : 0.f);
#pragma unroll
    for (int o = 16; o; o >>= 1) e += __shfl_xor_sync(0xffffffffu, e, o);
    float logZ = m + __logf(e);

    float acc = 0.f;
    for (int s = 1 + l; s < S_; s += 32) {
        int tp = tags[b * S_ + s - 1];
        int tc = tags[b * S_ + s];
        acc += trans[tp * T_ + tc] + g_emis[((size_t)s * B_ + b) * T_ + tc];
    }
#pragma unroll
    for (int o = 16; o; o >>= 1) acc += __shfl_xor_sync(0xffffffffu, acc, o);

    if (l == 0) {
        int t0 = tags[b * S_];
        int tl = tags[b * S_ + S_ - 1];
        g_res[b] = logZ - (start_t[t0] + g_emis[(size_t)b * T_ + t0] + acc + end_t[tl]);
    }
}

// ---------------------------------------------------------------------------
// K5: final mean
// ---------------------------------------------------------------------------
__global__ void k_final(float* __restrict__ out)
{
    __shared__ float red[4];
    int t = threadIdx.x;
    float v = g_res[t];
#pragma unroll
    for (int o = 16; o; o >>= 1) v += __shfl_xor_sync(0xffffffffu, v, o);
    if ((t & 31) == 0) red[t >> 5] = v;
    __syncthreads();
    if (t == 0) out[0] = (red[0] + red[1] + red[2] + red[3]) * (1.f / (float)B_);
}

// ---------------------------------------------------------------------------
// Launch
// ---------------------------------------------------------------------------
extern "C" void kernel_launch(void* const* d_in, const int* in_sizes, int n_in,
                              void* d_out, int out_size)
{
    const int*   sent  = (const int*)  d_in[0];
    const int*   tags  = (const int*)  d_in[1];
    const float* emb   = (const float*)d_in[3];
    const float* wih_f = (const float*)d_in[4];
    const float* whh_f = (const float*)d_in[5];
    const float* bih_f = (const float*)d_in[6];
    const float* bhh_f = (const float*)d_in[7];
    const float* wih_b = (const float*)d_in[8];
    const float* whh_b = (const float*)d_in[9];
    const float* bih_b = (const float*)d_in[10];
    const float* bhh_b = (const float*)d_in[11];
    const float* Wout  = (const float*)d_in[12];
    const float* bout  = (const float*)d_in[13];
    const float* strt  = (const float*)d_in[14];
    const float* endt  = (const float*)d_in[15];
    const float* trans = (const float*)d_in[16];
    float* out = (float*)d_out;

    const int input_smem = 100352;
    const int lstm_smem  = 16384 + 131072 + 1024;   // 2 h bufs + W slice + align
    const int emis_smem  = 197888;
    cudaFuncSetAttribute(k_input, cudaFuncAttributeMaxDynamicSharedMemorySize, input_smem);
    cudaFuncSetAttribute(k_lstm,  cudaFuncAttributeMaxDynamicSharedMemorySize, lstm_smem);
    cudaFuncSetAttribute(k_emis,  cudaFuncAttributeMaxDynamicSharedMemorySize, emis_smem);

    int nconv = (EMB2 + 2 * WIH2 + WOUT2 + 255) / 256;
    k_convert<<<nconv, 256>>>(emb, wih_f, wih_b, Wout);
    k_input<<<dim3(8, 2, 1024), 256, input_smem>>>(sent, bih_f, bhh_f, bih_b, bhh_b);
    k_lstm<<<64, 128, lstm_smem>>>(whh_f, whh_b);
    k_emis<<<512, 128, emis_smem>>>(bout);
    k_crf<<<128, 32>>>(trans, strt, endt, tags);
    k_final<<<1, 128>>>(out);
}

// round 17
// speedup vs baseline: 1.2336x; 1.0262x over previous
#include <cuda_runtime.h>
#include <cuda_bf16.h>
#include <math.h>

#define V_   50000
#define E_   256
#define H_   256
#define G4_  1024
#define HD_  512
#define T_   50
#define B_   128
#define S_   512

typedef unsigned long long u64;
typedef unsigned int u32;

// ---------------------------------------------------------------------------
// Device scratch
// ---------------------------------------------------------------------------
__device__ __nv_bfloat16 g_embb[(size_t)V_ * E_];
__device__ __nv_bfloat16 g_wihb[(size_t)2 * G4_ * E_];
__device__ __nv_bfloat16 g_woutb[(size_t)64 * HD_];        // padded [64][512]
__device__ __nv_bfloat16 g_Gb[(size_t)2 * S_ * B_ * G4_];  // [d][s][b][j]
__device__ __nv_bfloat16 g_hb[(size_t)2 * S_ * B_ * H_];   // [d][s][b][k]
__device__ __align__(16) float g_emis[(size_t)S_ * B_ * T_];
__device__ float g_res[B_];

// ---------------------------------------------------------------------------
// Helpers
// ---------------------------------------------------------------------------
__device__ __forceinline__ u64 pk2(float lo, float hi) {
    u64 r; asm("mov.b64 %0, {%1, %2};" : "=l"(r) : "f"(lo), "f"(hi)); return r;
}
__device__ __forceinline__ u64 f2ma(u64 a, u64 b, u64 c) {
    u64 d; asm("fma.rn.f32x2 %0, %1, %2, %3;" : "=l"(d) : "l"(a), "l"(b), "l"(c)); return d;
}
__device__ __forceinline__ u64 f2add(u64 a, u64 b) {
    u64 d; asm("add.rn.f32x2 %0, %1, %2;" : "=l"(d) : "l"(a), "l"(b)); return d;
}
__device__ __forceinline__ float2 upk(u64 v) {
    float2 f; asm("mov.b64 {%0, %1}, %2;" : "=f"(f.x), "=f"(f.y) : "l"(v)); return f;
}
__device__ __forceinline__ u32 smem_u32(const void* p) { return (u32)__cvta_generic_to_shared(p); }
__device__ __forceinline__ void cp16(void* smem, const void* g) {
    asm volatile("cp.async.cg.shared.global [%0], [%1], 16;" :: "r"(smem_u32(smem)), "l"(g));
}
#define CP_COMMIT() asm volatile("cp.async.commit_group;")
#define CP_WAITN(n) asm volatile("cp.async.wait_group %0;" :: "n"(n))

__device__ __forceinline__ u32 bfpack(float lo, float hi) {
    u32 r; asm("cvt.rn.bf16x2.f32 %0, %1, %2;" : "=r"(r) : "f"(hi), "f"(lo)); return r;
}
__device__ __forceinline__ float tanhx(float x) {
    float r; asm("tanh.approx.f32 %0, %1;" : "=f"(r) : "f"(x)); return r;
}
__device__ __forceinline__ float sigx(float x) { return 0.5f * tanhx(0.5f * x) + 0.5f; }

__device__ __forceinline__ void ldsm4(u32& r0, u32& r1, u32& r2, u32& r3, u32 addr) {
    asm volatile("ldmatrix.sync.aligned.m8n8.x4.shared.b16 {%0,%1,%2,%3}, [%4];"
                 : "=r"(r0), "=r"(r1), "=r"(r2), "=r"(r3) : "r"(addr));
}
__device__ __forceinline__ void ldsm2(u32& r0, u32& r1, u32 addr) {
    asm volatile("ldmatrix.sync.aligned.m8n8.x2.shared.b16 {%0,%1}, [%2];"
                 : "=r"(r0), "=r"(r1) : "r"(addr));
}
__device__ __forceinline__ void hmma(float* d, u32 a0, u32 a1, u32 a2, u32 a3, u32 b0, u32 b1) {
    asm volatile(
        "mma.sync.aligned.m16n8k16.row.col.f32.bf16.bf16.f32 "
        "{%0,%1,%2,%3}, {%4,%5,%6,%7}, {%8,%9}, {%0,%1,%2,%3};"
        : "+f"(d[0]), "+f"(d[1]), "+f"(d[2]), "+f"(d[3])
        : "r"(a0), "r"(a1), "r"(a2), "r"(a3), "r"(b0), "r"(b1));
}

// ---------------------------------------------------------------------------
// K0: convert emb + W_ih + W_out(padded to 64 rows) to bf16
// ---------------------------------------------------------------------------
#define EMB2  ((V_ * E_) / 2)
#define WIH2  ((G4_ * E_) / 2)
#define WOUT2 ((64 * HD_) / 2)
__global__ void __launch_bounds__(256) k_convert(
    const float* __restrict__ emb, const float* __restrict__ wf,
    const float* __restrict__ wb,  const float* __restrict__ wo)
{
    int i = blockIdx.x * 256 + threadIdx.x;
    if (i >= EMB2 + 2 * WIH2 + WOUT2) return;
    float2 v; __nv_bfloat162* dst;
    if (i < EMB2)                 { v = ((const float2*)emb)[i];              dst = (__nv_bfloat162*)g_embb + i; }
    else if (i < EMB2 + WIH2)     { v = ((const float2*)wf)[i - EMB2];        dst = (__nv_bfloat162*)g_wihb + (i - EMB2); }
    else if (i < EMB2 + 2 * WIH2) { v = ((const float2*)wb)[i - EMB2 - WIH2]; dst = (__nv_bfloat162*)g_wihb + (i - EMB2); }
    else {
        int j = i - EMB2 - 2 * WIH2;
        int tag = (j * 2) >> 9, k = (j * 2) & 511;
        v.x = (tag < T_) ? wo[(size_t)tag * HD_ + k] : 0.f;
        v.y = (tag < T_) ? wo[(size_t)tag * HD_ + k + 1] : 0.f;
        dst = (__nv_bfloat162*)g_woutb + j;
    }
    *dst = __floats2bfloat162_rn(v.x, v.y);
}

// ---------------------------------------------------------------------------
// K1: input projection via mma.sync bf16. grid (8 jt, 2 d, 1024), blk 256.
// ---------------------------------------------------------------------------
__global__ void __launch_bounds__(256) k_input(
    const int* __restrict__ sent,
    const float* __restrict__ bih_f, const float* __restrict__ bhh_f,
    const float* __restrict__ bih_b, const float* __restrict__ bhh_b)
{
    extern __shared__ __align__(16) char smraw[];
    char* sm = smraw + ((1024 - (smem_u32(smraw) & 1023)) & 1023);
    char* smB  = sm;                     // 64KB W tile
    char* smA  = sm + 65536;             // 32KB emb tile
    int*  toks = (int*)(sm + 98304);
    float* bsm = (float*)(sm + 98560);

    const int jt = blockIdx.x, d = blockIdx.y;
    const int s  = blockIdx.z >> 1;
    const int bh = blockIdx.z & 1;
    const int j0 = jt * 128;
    const int t = threadIdx.x;
    const int l = t & 31, w = t >> 5;
    const int wm = w & 1, wn = w >> 1;

    if (t < 64) toks[t] = sent[(bh * 64 + t) * S_ + s];
    if (t < 128) {
        const float* bi = d ? bih_b : bih_f;
        const float* bh_ = d ? bhh_b : bhh_f;
        bsm[t] = bi[j0 + t] + bh_[j0 + t];
    }
    __syncthreads();

    for (int i = t; i < 4096; i += 256) {
        int row = i >> 5, c = i & 31;
        cp16(smB + row * 512 + ((c ^ (row & 7)) * 16),
             (const char*)(g_wihb + ((size_t)d * G4_ + j0 + row) * E_) + c * 16);
    }
    for (int i = t; i < 2048; i += 256) {
        int row = i >> 5, c = i & 31;
        cp16(smA + row * 512 + ((c ^ (row & 7)) * 16),
             (const char*)(g_embb + (size_t)toks[row] * E_) + c * 16);
    }
    CP_COMMIT();
    CP_WAITN(0);
    __syncthreads();

    const u32 smB_b = smem_u32(smB), smA_b = smem_u32(smA);

    float acc[2][4][4];
#pragma unroll
    for (int m = 0; m < 2; m++)
#pragma unroll
        for (int n = 0; n < 4; n++)
#pragma unroll
            for (int q = 0; q < 4; q++) acc[m][n][q] = 0.f;

#pragma unroll 4
    for (int kk = 0; kk < 16; kk++) {
        u32 a[2][4];
#pragma unroll
        for (int m = 0; m < 2; m++) {
            int row = wm * 32 + m * 16 + (l & 15);
            int c = kk * 2 + (l >> 4);
            ldsm4(a[m][0], a[m][1], a[m][2], a[m][3],
                  smA_b + row * 512 + ((c ^ (row & 7)) * 16));
        }
#pragma unroll
        for (int nt = 0; nt < 4; nt++) {
            int row = wn * 32 + nt * 8 + (l & 7);
            int c = kk * 2 + ((l >> 3) & 1);
            u32 b0, b1;
            ldsm2(b0, b1, smB_b + row * 512 + ((c ^ (row & 7)) * 16));
#pragma unroll
            for (int m = 0; m < 2; m++)
                hmma(acc[m][nt], a[m][0], a[m][1], a[m][2], a[m][3], b0, b1);
        }
    }

    __nv_bfloat16* Gbase = g_Gb + ((size_t)(d * S_ + s) * B_) * G4_;
#pragma unroll
    for (int m = 0; m < 2; m++)
#pragma unroll
    for (int nt = 0; nt < 4; nt++) {
        int r  = wm * 32 + m * 16 + (l >> 2);
        int jl = wn * 32 + nt * 8 + 2 * (l & 3);
        float b0 = bsm[jl], b1 = bsm[jl + 1];
        size_t bg = (size_t)(bh * 64 + r);
        *(u32*)(Gbase + bg * G4_ + j0 + jl)       = bfpack(acc[m][nt][0] + b0, acc[m][nt][1] + b1);
        *(u32*)(Gbase + (bg + 8) * G4_ + j0 + jl) = bfpack(acc[m][nt][2] + b0, acc[m][nt][3] + b1);
    }
}

// ---------------------------------------------------------------------------
// K2: persistent bidirectional LSTM, DSMEM clusters of 8. grid 128, blk 128.
// CTA = (d = cta>>6, bg = (cta>>3)&7, us = cta&7 = cluster rank):
// 16 batch rows x 32 units, all 4 gates local (M=16, N=128, K=256; W 64KB).
// Halves per-CTA MMA vs cluster-4 (64 HMMA/warp) and uses all 128 SMs.
// h exchange: each CTA writes its 1KB h slice into all 8 peers' smem
// (double-buffered); one cluster barrier per step with G prefetch between
// arrive and wait. mapa rank deltas hoisted out of the loop.
// ---------------------------------------------------------------------------
__global__ void __launch_bounds__(128, 1) __cluster_dims__(8, 1, 1)
k_lstm(const float* __restrict__ whh_f, const float* __restrict__ whh_b)
{
    extern __shared__ __align__(16) char smraw[];
    char* sm   = smraw + ((1024 - (smem_u32(smraw) & 1023)) & 1023);
    char* smA0 = sm;                 // 8KB h tile buf0 [16 b][512B]
    char* smA1 = sm + 8192;          // 8KB h tile buf1
    char* smW  = sm + 16384;         // 64KB W slice [128 j][512B]

    const int cta = blockIdx.x;
    const int d   = cta >> 6;
    const int bg  = (cta >> 3) & 7;
    const int b0  = bg * 16;
    const int us  = cta & 7;         // cluster rank
    const int U0  = us * 32;
    const int t   = threadIdx.x;
    const int l = t & 31, w = t >> 5;
    const float* __restrict__ Wh = d ? whh_b : whh_f;

    // Load W slice: smem row j = g*32 + ul  <-  Wh[g*256 + U0 + ul][k]
    for (int i = t; i < 128 * 64; i += 128) {
        int row = i >> 6, k4 = (i & 63) * 4;
        int g = row >> 5, ul = row & 31;
        float4 v = *(const float4*)&Wh[(size_t)(g * 256 + U0 + ul) * H_ + k4];
        int c = k4 >> 3, off = (k4 * 2) & 15;
        char* p = smW + row * 512 + ((c ^ (row & 7)) * 16) + off;
        *(u32*)p       = bfpack(v.x, v.y);
        *(u32*)(p + 4) = bfpack(v.z, v.w);
    }
    {   // zero buf0 (step-0 h_prev = 0)
        uint4 z = make_uint4(0, 0, 0, 0);
        for (int i = t; i < 512; i += 128) ((uint4*)smA0)[i] = z;
    }
    __syncthreads();

    const u32 smA0_b = smem_u32(smA0), smA1_b = smem_u32(smA1), smW_b = smem_u32(smW);
    const int u2 = 2 * (l & 3);

    // DSMEM rank deltas (segment offsets are rank-constant)
    u32 rdelta[8];
#pragma unroll
    for (int r = 0; r < 8; r++) {
        u32 ra;
        asm("mapa.shared::cluster.u32 %0, %1, %2;" : "=r"(ra) : "r"(smA0_b), "r"(r));
        rdelta[r] = ra - smA0_b;
    }

    float cst[4];
#pragma unroll
    for (int u = 0; u < 4; u++) cst[u] = 0.f;

    const __nv_bfloat16* Gd = g_Gb + (size_t)d * S_ * B_ * G4_;
    __nv_bfloat16*       Hd = g_hb + (size_t)d * S_ * B_ * H_;

    // gq layout: [hi*4 + g]
    u32 gq[8], gqn[8];
    auto gload = [&](u32* dst, int ss) {
        const __nv_bfloat16* Gp = Gd + (size_t)ss * B_ * G4_;
#pragma unroll
        for (int hi = 0; hi < 2; hi++) {
            int b = b0 + (l >> 2) + hi * 8;
#pragma unroll
            for (int g = 0; g < 4; g++)
                dst[hi * 4 + g] =
                    *(const u32*)(Gp + (size_t)b * G4_ + g * 256 + U0 + w * 8 + u2);
        }
    };
    gload(gqn, d ? S_ - 1 : 0);

    for (int step = 0; step < S_; step++) {
        const int s = d ? (S_ - 1 - step) : step;
        const u32 rdA = (step & 1) ? smA1_b : smA0_b;
        const u32 wrA = (step & 1) ? smA0_b : smA1_b;

#pragma unroll
        for (int j = 0; j < 8; j++) gq[j] = gqn[j];

        float acc[4][4];
#pragma unroll
        for (int g = 0; g < 4; g++)
#pragma unroll
            for (int q = 0; q < 4; q++) acc[g][q] = 0.f;

        if (step > 0) {
#pragma unroll
            for (int kk = 0; kk < 16; kk++) {
                u32 a0r, a1r, a2r, a3r;
                {
                    int row = l & 15;
                    int c = kk * 2 + (l >> 4);
                    ldsm4(a0r, a1r, a2r, a3r, rdA + row * 512 + ((c ^ (row & 7)) * 16));
                }
#pragma unroll
                for (int g = 0; g < 4; g++) {
                    int row = g * 32 + w * 8 + (l & 7);
                    int c = kk * 2 + ((l >> 3) & 1);
                    u32 b0r, b1r;
                    ldsm2(b0r, b1r, smW_b + row * 512 + ((c ^ (row & 7)) * 16));
                    hmma(acc[g], a0r, a1r, a2r, a3r, b0r, b1r);
                }
            }
        }

        // combine + store h (global for k_emis, DSMEM peers for next step)
        const bool more = (step + 1 < S_);
#pragma unroll
        for (int hi = 0; hi < 2; hi++) {
            const int br = (l >> 2) + hi * 8;
            const int e = 2 * hi;
            float2 gi = __bfloat1622float2(*(const __nv_bfloat162*)&gq[hi * 4 + 0]);
            float2 gf = __bfloat1622float2(*(const __nv_bfloat162*)&gq[hi * 4 + 1]);
            float2 gg = __bfloat1622float2(*(const __nv_bfloat162*)&gq[hi * 4 + 2]);
            float2 go = __bfloat1622float2(*(const __nv_bfloat162*)&gq[hi * 4 + 3]);
            const int ci = 2 * hi;
            float c0 = sigx(acc[1][e] + gf.x) * cst[ci]
                     + sigx(acc[0][e] + gi.x) * tanhx(acc[2][e] + gg.x);
            cst[ci] = c0;
            float h0 = sigx(acc[3][e] + go.x) * tanhx(c0);
            float c1 = sigx(acc[1][e + 1] + gf.y) * cst[ci + 1]
                     + sigx(acc[0][e + 1] + gi.y) * tanhx(acc[2][e + 1] + gg.y);
            cst[ci + 1] = c1;
            float h1 = sigx(acc[3][e + 1] + go.y) * tanhx(c1);
            u32 hv = bfpack(h0, h1);
            *(u32*)(Hd + ((size_t)s * B_ + b0 + br) * H_ + U0 + w * 8 + u2) = hv;
            if (more) {
                int bo = 2 * (U0 + w * 8 + u2);
                u32 laddr = wrA + br * 512 + ((((bo >> 4) ^ (br & 7)) << 4) | (bo & 15));
#pragma unroll
                for (int r = 0; r < 8; r++) {
                    asm volatile("st.shared::cluster.u32 [%0], %1;"
                                 :: "r"(laddr + rdelta[r]), "r"(hv) : "memory");
                }
            }
        }

        // one cluster barrier per step; G prefetch rides between arrive/wait
        if (more) {
            asm volatile("barrier.cluster.arrive.aligned;" ::: "memory");
            gload(gqn, d ? (S_ - 2 - step) : (step + 1));
            asm volatile("barrier.cluster.wait.aligned;" ::: "memory");
        }
    }
}

// ---------------------------------------------------------------------------
// K3: emissions via mma.sync. grid 512 (s), block 128.
// ---------------------------------------------------------------------------
__global__ void __launch_bounds__(128) k_emis(const float* __restrict__ bo)
{
    extern __shared__ __align__(16) char smraw[];
    char* sm = smraw + ((1024 - (smem_u32(smraw) & 1023)) & 1023);
    char* smW  = sm;
    char* smA0 = sm + 65536;
    char* smA1 = sm + 131072;
    float* bsm = (float*)(sm + 196608);

    const int s = blockIdx.x;
    const int t = threadIdx.x;
    const int l = t & 31, w = t >> 5;

    if (t < 64) bsm[t] = (t < T_) ? bo[t] : 0.f;

    for (int i = t; i < 4096; i += 128) {
        int row = i >> 6, c = i & 63;
        cp16(smW + row * 1024 + ((c ^ (row & 7)) * 16),
             (const char*)g_woutb + row * 1024 + c * 16);
    }
    CP_COMMIT();
    for (int i = t; i < 4096; i += 128) {
        int row = i >> 5, c = i & 31;
        cp16(smA0 + row * 512 + ((c ^ (row & 7)) * 16),
             (const char*)(g_hb + ((size_t)s * B_ + row) * H_) + c * 16);
    }
    CP_COMMIT();
    for (int i = t; i < 4096; i += 128) {
        int row = i >> 5, c = i & 31;
        cp16(smA1 + row * 512 + ((c ^ (row & 7)) * 16),
             (const char*)(g_hb + (size_t)S_ * B_ * H_ + ((size_t)s * B_ + row) * H_) + c * 16);
    }
    CP_COMMIT();

    const u32 smW_b = smem_u32(smW);

    float acc[2][8][4];
#pragma unroll
    for (int m = 0; m < 2; m++)
#pragma unroll
        for (int n = 0; n < 8; n++)
#pragma unroll
            for (int q = 0; q < 4; q++) acc[m][n][q] = 0.f;

    auto stage = [&](u32 smA_b, int wc0) {
#pragma unroll 4
        for (int kk = 0; kk < 16; kk++) {
            u32 a[2][4];
#pragma unroll
            for (int m = 0; m < 2; m++) {
                int row = w * 32 + m * 16 + (l & 15);
                int c = kk * 2 + (l >> 4);
                ldsm4(a[m][0], a[m][1], a[m][2], a[m][3],
                      smA_b + row * 512 + ((c ^ (row & 7)) * 16));
            }
#pragma unroll
            for (int nt = 0; nt < 8; nt++) {
                int row = nt * 8 + (l & 7);
                int c = wc0 + kk * 2 + ((l >> 3) & 1);
                u32 b0, b1;
                ldsm2(b0, b1, smW_b + row * 1024 + ((c ^ (row & 7)) * 16));
#pragma unroll
                for (int m = 0; m < 2; m++)
                    hmma(acc[m][nt], a[m][0], a[m][1], a[m][2], a[m][3], b0, b1);
            }
        }
    };

    CP_WAITN(1);
    __syncthreads();
    stage(smem_u32(smA0), 0);
    CP_WAITN(0);
    __syncthreads();
    stage(smem_u32(smA1), 32);

#pragma unroll
    for (int m = 0; m < 2; m++)
#pragma unroll
    for (int nt = 0; nt < 8; nt++) {
        int r  = w * 32 + m * 16 + (l >> 2);
        int jl = nt * 8 + 2 * (l & 3);
        if (jl < T_) {
            float b0 = bsm[jl], b1 = bsm[jl + 1];
            *(float2*)(g_emis + ((size_t)s * B_ + r) * T_ + jl)     = make_float2(acc[m][nt][0] + b0, acc[m][nt][1] + b1);
            *(float2*)(g_emis + ((size_t)s * B_ + r + 8) * T_ + jl) = make_float2(acc[m][nt][2] + b0, acc[m][nt][3] + b1);
        }
    }
}

// ---------------------------------------------------------------------------
// K4: CRF — one warp per batch element, 128 CTAs; exp(trans) in registers.
// ---------------------------------------------------------------------------
__global__ void __launch_bounds__(32) k_crf(
    const float* __restrict__ trans, const float* __restrict__ start_t,
    const float* __restrict__ end_t, const int* __restrict__ tags)
{
    __shared__ float pw[64];

    const int b = blockIdx.x;
    const int l = threadIdx.x;
    const bool v1 = (l + 32 < T_);

    u64 eT[T_];
#pragma unroll
    for (int tt = 0; tt < T_; tt++) {
        float e0 = expf(trans[tt * T_ + l]);
        float e1 = v1 ? expf(trans[tt * T_ + l + 32]) : 0.f;
        eT[tt] = pk2(e0, e1);
    }

    float a0 = start_t[l] + g_emis[(size_t)b * T_ + l];
    float a1 = v1 ? (start_t[l + 32] + g_emis[(size_t)b * T_ + l + 32]) : -1e30f;

    float e0n = g_emis[((size_t)B_ + b) * T_ + l];
    float e1n = v1 ? g_emis[((size_t)B_ + b) * T_ + l + 32] : 0.f;

    for (int s = 1; s < S_; s++) {
        float e0 = e0n, e1 = e1n;
        if (s + 1 < S_) {
            const float* es = g_emis + ((size_t)(s + 1) * B_ + b) * T_;
            e0n = es[l];
            e1n = v1 ? es[l + 32] : 0.f;
        }

        float m = __shfl_sync(0xffffffffu, a0, 0);
        pw[l]      = __expf(a0 - m);
        pw[l + 32] = v1 ? __expf(a1 - m) : 0.f;
        __syncwarp();

        u64 q0 = 0ull, q1 = 0ull, q2 = 0ull, q3 = 0ull;
#pragma unroll
        for (int tt = 0; tt < 48; tt += 4) {
            q0 = f2ma(pk2(pw[tt],     pw[tt]),     eT[tt],     q0);
            q1 = f2ma(pk2(pw[tt + 1], pw[tt + 1]), eT[tt + 1], q1);
            q2 = f2ma(pk2(pw[tt + 2], pw[tt + 2]), eT[tt + 2], q2);
            q3 = f2ma(pk2(pw[tt + 3], pw[tt + 3]), eT[tt + 3], q3);
        }
        q0 = f2ma(pk2(pw[48], pw[48]), eT[48], q0);
        q1 = f2ma(pk2(pw[49], pw[49]), eT[49], q1);
        float2 qf = upk(f2add(f2add(q0, q1), f2add(q2, q3)));
        a0 = m + __logf(qf.x) + e0;
        a1 = v1 ? (m + __logf(qf.y) + e1) : -1e30f;
        __syncwarp();
    }

    float vv0 = a0 + end_t[l];
    float vv1 = v1 ? (a1 + end_t[l + 32]) : -1e30f;
    float m = fmaxf(vv0, vv1);
#pragma unroll
    for (int o = 16; o; o >>= 1) m = fmaxf(m, __shfl_xor_sync(0xffffffffu, m, o));
    float e = __expf(vv0 - m) + (v1 ? __expf(vv1 - m) : 0.f);
#pragma unroll
    for (int o = 16; o; o >>= 1) e += __shfl_xor_sync(0xffffffffu, e, o);
    float logZ = m + __logf(e);

    float acc = 0.f;
    for (int s = 1 + l; s < S_; s += 32) {
        int tp = tags[b * S_ + s - 1];
        int tc = tags[b * S_ + s];
        acc += trans[tp * T_ + tc] + g_emis[((size_t)s * B_ + b) * T_ + tc];
    }
#pragma unroll
    for (int o = 16; o; o >>= 1) acc += __shfl_xor_sync(0xffffffffu, acc, o);

    if (l == 0) {
        int t0 = tags[b * S_];
        int tl = tags[b * S_ + S_ - 1];
        g_res[b] = logZ - (start_t[t0] + g_emis[(size_t)b * T_ + t0] + acc + end_t[tl]);
    }
}

// ---------------------------------------------------------------------------
// K5: final mean
// ---------------------------------------------------------------------------
__global__ void k_final(float* __restrict__ out)
{
    __shared__ float red[4];
    int t = threadIdx.x;
    float v = g_res[t];
#pragma unroll
    for (int o = 16; o; o >>= 1) v += __shfl_xor_sync(0xffffffffu, v, o);
    if ((t & 31) == 0) red[t >> 5] = v;
    __syncthreads();
    if (t == 0) out[0] = (red[0] + red[1] + red[2] + red[3]) * (1.f / (float)B_);
}

// ---------------------------------------------------------------------------
// Launch
// ---------------------------------------------------------------------------
extern "C" void kernel_launch(void* const* d_in, const int* in_sizes, int n_in,
                              void* d_out, int out_size)
{
    const int*   sent  = (const int*)  d_in[0];
    const int*   tags  = (const int*)  d_in[1];
    const float* emb   = (const float*)d_in[3];
    const float* wih_f = (const float*)d_in[4];
    const float* whh_f = (const float*)d_in[5];
    const float* bih_f = (const float*)d_in[6];
    const float* bhh_f = (const float*)d_in[7];
    const float* wih_b = (const float*)d_in[8];
    const float* whh_b = (const float*)d_in[9];
    const float* bih_b = (const float*)d_in[10];
    const float* bhh_b = (const float*)d_in[11];
    const float* Wout  = (const float*)d_in[12];
    const float* bout  = (const float*)d_in[13];
    const float* strt  = (const float*)d_in[14];
    const float* endt  = (const float*)d_in[15];
    const float* trans = (const float*)d_in[16];
    float* out = (float*)d_out;

    const int input_smem = 100352;
    const int lstm_smem  = 16384 + 65536 + 1024;   // 2 h bufs + W slice + align
    const int emis_smem  = 197888;
    cudaFuncSetAttribute(k_input, cudaFuncAttributeMaxDynamicSharedMemorySize, input_smem);
    cudaFuncSetAttribute(k_lstm,  cudaFuncAttributeMaxDynamicSharedMemorySize, lstm_smem);
    cudaFuncSetAttribute(k_emis,  cudaFuncAttributeMaxDynamicSharedMemorySize, emis_smem);

    int nconv = (EMB2 + 2 * WIH2 + WOUT2 + 255) / 256;
    k_convert<<<nconv, 256>>>(emb, wih_f, wih_b, Wout);
    k_input<<<dim3(8, 2, 1024), 256, input_smem>>>(sent, bih_f, bhh_f, bih_b, bhh_b);
    k_lstm<<<128, 128, lstm_smem>>>(whh_f, whh_b);
    k_emis<<<512, 128, emis_smem>>>(bout);
    k_crf<<<128, 32>>>(trans, strt, endt, tags);
    k_final<<<1, 128>>>(out);
}